// round 1
// baseline (speedup 1.0000x reference)
#include <cuda_runtime.h>

#define PPR       128   // points per ray (tile size, one CTA per ray)
#define PAD       130   // smem activation row stride in floats (8B-aligned, low STS conflicts)
#define NTHREADS  512
#define WCHUNK    64    // weight rows staged in smem per chunk

typedef unsigned long long ull;

__device__ __forceinline__ ull pack2(float lo, float hi) {
    ull r; asm("mov.b64 %0, {%1, %2};" : "=l"(r) : "f"(lo), "f"(hi)); return r;
}
__device__ __forceinline__ void unpack2(ull v, float &lo, float &hi) {
    asm("mov.b64 {%0, %1}, %2;" : "=f"(lo), "=f"(hi) : "l"(v));
}
__device__ __forceinline__ void fma2(ull &d, ull a, ull b) {
    asm("fma.rn.f32x2 %0, %1, %2, %0;" : "+l"(d) : "l"(a), "l"(b));
}

// One fused MLP layer over a tile of 128 points.
// Output channels CC = 32*JMAX (128 or 64). Thread (chg, ptg) computes channels
// {chg + 32j} for 8 points {8*ptg .. 8*ptg+7}. Input activations come from up to
// two smem segments (for concat/skip layers), k-major with row stride PAD.
// Weights gW are global row-major [Ktot][wstride]; we use columns
// [coloff, coloff+CC). Weight rows are staged through the smem chunk buffer.
template <int JMAX>
__device__ __forceinline__ void mlp_layer(
    const float* __restrict__ gW, int wstride, int coloff,
    const float* __restrict__ gB,
    const float* __restrict__ seg0, int n0,
    const float* __restrict__ seg1, int n1,
    float* __restrict__ dst, bool do_relu,
    float* __restrict__ Wbuf,
    int tid, int chg, int ptg)
{
    constexpr int CC = 32 * JMAX;

    ull acc[JMAX][4];
#pragma unroll
    for (int j = 0; j < JMAX; j++) {
        float b = gB[chg + 32 * j];
        ull bb = pack2(b, b);
#pragma unroll
        for (int pp = 0; pp < 4; pp++) acc[j][pp] = bb;
    }

    const float* segs[2] = { seg0, seg1 };
    int          lens[2] = { n0, n1 };

    int wrow = 0;  // running row offset into gW
#pragma unroll
    for (int si = 0; si < 2; si++) {
        const float* base = segs[si];
        int n = lens[si];
        for (int s = 0; s < n; s += WCHUNK) {
            int nk = min(WCHUNK, n - s);
            __syncthreads();  // previous chunk consumers done before Wbuf overwrite
            // cooperative load of W chunk (coalesced: consecutive i -> consecutive cols)
            for (int i = tid; i < nk * CC; i += NTHREADS) {
                int r = i / CC;
                int c = i - r * CC;
                Wbuf[i] = gW[(wrow + s + r) * wstride + coloff + c];
            }
            __syncthreads();

            const float* arow = base + s * PAD + 8 * ptg;
            const float* wrowp = Wbuf + chg;
#pragma unroll 4
            for (int kk = 0; kk < nk; kk++) {
                const ull* ap = (const ull*)(arow + kk * PAD);  // 8B-aligned (PAD even)
                ull a0 = ap[0];  // points p0,p1 (broadcast LDS.64 within warp)
                ull a1 = ap[1];
                ull a2 = ap[2];
                ull a3 = ap[3];
                const float* wk = wrowp + kk * CC;
#pragma unroll
                for (int j = 0; j < JMAX; j++) {
                    float w = wk[32 * j];      // conflict-free scalar LDS
                    ull ww = pack2(w, w);
                    fma2(acc[j][0], a0, ww);
                    fma2(acc[j][1], a1, ww);
                    fma2(acc[j][2], a2, ww);
                    fma2(acc[j][3], a3, ww);
                }
            }
        }
        wrow += n;
    }

    // epilogue: (relu) + store, k-major [c][p]
#pragma unroll
    for (int j = 0; j < JMAX; j++) {
        int c = chg + 32 * j;
        float* drow = dst + c * PAD + 8 * ptg;
#pragma unroll
        for (int pp = 0; pp < 4; pp++) {
            float lo, hi;
            unpack2(acc[j][pp], lo, hi);
            if (do_relu) { lo = fmaxf(lo, 0.f); hi = fmaxf(hi, 0.f); }
            *(ull*)(drow + 2 * pp) = pack2(lo, hi);
        }
    }
    __syncthreads();
}

__global__ void __launch_bounds__(NTHREADS, 1)
nerf_fused_kernel(
    const float* __restrict__ pts, const float* __restrict__ dirs,
    const float* __restrict__ w0, const float* __restrict__ b0,
    const float* __restrict__ w1, const float* __restrict__ b1,
    const float* __restrict__ w2, const float* __restrict__ b2,
    const float* __restrict__ w3, const float* __restrict__ b3,
    const float* __restrict__ w4, const float* __restrict__ b4,
    const float* __restrict__ w5, const float* __restrict__ b5,
    const float* __restrict__ wd, const float* __restrict__ bd,
    const float* __restrict__ wr1, const float* __restrict__ br1,
    const float* __restrict__ wr2, const float* __restrict__ br2,
    float* __restrict__ out, int n_rays)
{
    extern __shared__ float sm[];
    float* bufA = sm;                       // 128 x PAD
    float* bufB = bufA + 128 * PAD;         // 128 x PAD
    float* xyzb = bufB + 128 * PAD;         // 39  x PAD (xyz harmonic embed, kept for skip)
    float* dirb = xyzb + 39 * PAD;          // 15  x PAD (dir embed replicated across points)
    float* Wbuf = dirb + 15 * PAD;          // WCHUNK x 128

    int ray = blockIdx.x;
    int tid = threadIdx.x;
    int chg = tid & 31;
    int ptg = tid >> 5;

    // ---- embeddings ----
    if (tid < PPR) {
        int p = tid;
        const float* pp3 = pts + ((long long)ray * PPR + p) * 3;
#pragma unroll
        for (int c = 0; c < 3; c++) {
            float v = pp3[c];
            float fr = 1.f;
#pragma unroll
            for (int f = 0; f < 6; f++) {
                float s, co;
                sincosf(v * fr, &s, &co);
                xyzb[(c * 6 + f) * PAD + p] = s;
                xyzb[(18 + c * 6 + f) * PAD + p] = co;
                fr *= 2.f;
            }
            xyzb[(36 + c) * PAD + p] = v;
        }
        const float* dd = dirs + (long long)ray * 3;
#pragma unroll
        for (int c = 0; c < 3; c++) {
            float v = dd[c];
            float fr = 1.f;
#pragma unroll
            for (int f = 0; f < 2; f++) {
                float s, co;
                sincosf(v * fr, &s, &co);
                dirb[(c * 2 + f) * PAD + p] = s;
                dirb[(6 + c * 2 + f) * PAD + p] = co;
                fr *= 2.f;
            }
            dirb[(12 + c) * PAD + p] = v;
        }
    }
    __syncthreads();

    // ---- trunk MLP ----
    mlp_layer<4>(w0, 128, 0, b0, xyzb, 39, nullptr, 0, bufA, true,  Wbuf, tid, chg, ptg);
    mlp_layer<4>(w1, 128, 0, b1, bufA, 128, nullptr, 0, bufB, true, Wbuf, tid, chg, ptg);
    mlp_layer<4>(w2, 128, 0, b2, bufB, 128, nullptr, 0, bufA, true, Wbuf, tid, chg, ptg);
    // skip layer: input = concat(y, xyz_embed)
    mlp_layer<4>(w3, 128, 0, b3, bufA, 128, xyzb, 39, bufB, true,  Wbuf, tid, chg, ptg);
    mlp_layer<4>(w4, 128, 0, b4, bufB, 128, nullptr, 0, bufA, true, Wbuf, tid, chg, ptg);
    mlp_layer<4>(w5, 128, 0, b5, bufA, 128, nullptr, 0, bufB, true, Wbuf, tid, chg, ptg);

    // ---- wd: columns 1..128 (the feature part), no relu. Input stays in bufB. ----
    mlp_layer<4>(wd, 129, 1, bd + 1, bufB, 128, nullptr, 0, bufA, false, Wbuf, tid, chg, ptg);

    // ---- density: column 0 of wd, computed from bufB (layer-5 output, still intact) ----
    if (tid < PPR) {
        int p = tid;
        float s = bd[0];
#pragma unroll 4
        for (int k = 0; k < 128; k++)
            s = fmaf(bufB[k * PAD + p], __ldg(&wd[k * 129]), s);
        out[(long long)ray * PPR + p] = fmaxf(s, 0.f);
    }
    // no explicit sync needed: wr1's internal __syncthreads precedes any bufB overwrite

    // ---- wr1: input = concat(x[1:129] (bufA), dir_embed (dirb)) -> 64, relu ----
    mlp_layer<2>(wr1, 64, 0, br1, bufA, 128, dirb, 15, bufB, true, Wbuf, tid, chg, ptg);

    // ---- wr2: 64 -> 3, sigmoid ----
    if (tid < PPR) {
        int p = tid;
        float r0 = br2[0], r1 = br2[1], r2 = br2[2];
#pragma unroll 4
        for (int k = 0; k < 64; k++) {
            float h = bufB[k * PAD + p];
            r0 = fmaf(h, __ldg(&wr2[k * 3 + 0]), r0);
            r1 = fmaf(h, __ldg(&wr2[k * 3 + 1]), r1);
            r2 = fmaf(h, __ldg(&wr2[k * 3 + 2]), r2);
        }
        long long N = (long long)n_rays * PPR;
        long long base = N + ((long long)ray * PPR + p) * 3;
        out[base + 0] = 1.f / (1.f + expf(-r0));
        out[base + 1] = 1.f / (1.f + expf(-r1));
        out[base + 2] = 1.f / (1.f + expf(-r2));
    }
}

extern "C" void kernel_launch(void* const* d_in, const int* in_sizes, int n_in,
                              void* d_out, int out_size)
{
    const float* pts  = (const float*)d_in[0];
    const float* dirs = (const float*)d_in[1];
    const float* w0 = (const float*)d_in[2];
    const float* b0 = (const float*)d_in[3];
    const float* w1 = (const float*)d_in[4];
    const float* b1 = (const float*)d_in[5];
    const float* w2 = (const float*)d_in[6];
    const float* b2 = (const float*)d_in[7];
    const float* w3 = (const float*)d_in[8];
    const float* b3 = (const float*)d_in[9];
    const float* w4 = (const float*)d_in[10];
    const float* b4 = (const float*)d_in[11];
    const float* w5 = (const float*)d_in[12];
    const float* b5 = (const float*)d_in[13];
    const float* wd = (const float*)d_in[14];
    const float* bd = (const float*)d_in[15];
    const float* wr1 = (const float*)d_in[16];
    const float* br1 = (const float*)d_in[17];
    const float* wr2 = (const float*)d_in[18];
    const float* br2 = (const float*)d_in[19];
    float* out = (float*)d_out;

    int n_rays = in_sizes[1] / 3;  // directions is [n_rays, 3]

    // dynamic smem: 2 act buffers + xyz embed + dir embed + weight chunk
    size_t smem = (size_t)(2 * 128 * PAD + 39 * PAD + 15 * PAD + WCHUNK * 128) * sizeof(float);
    cudaFuncSetAttribute(nerf_fused_kernel,
                         cudaFuncAttributeMaxDynamicSharedMemorySize, (int)smem);

    nerf_fused_kernel<<<n_rays, NTHREADS, smem>>>(
        pts, dirs, w0, b0, w1, b1, w2, b2, w3, b3, w4, b4, w5, b5,
        wd, bd, wr1, br1, wr2, br2, out, n_rays);
}

// round 2
// speedup vs baseline: 1.3395x; 1.3395x over previous
#include <cuda_runtime.h>

#define PPR       128   // points per ray (tile size, one CTA per ray)
#define PAD       130   // smem activation row stride in floats (8B-aligned, low STS conflicts)
#define NTHREADS  512
#define WCHUNK    64    // weight rows staged in smem per chunk

typedef unsigned long long ull;

__device__ __forceinline__ ull pack2(float lo, float hi) {
    ull r; asm("mov.b64 %0, {%1, %2};" : "=l"(r) : "f"(lo), "f"(hi)); return r;
}
__device__ __forceinline__ void unpack2(ull v, float &lo, float &hi) {
    asm("mov.b64 {%0, %1}, %2;" : "=f"(lo), "=f"(hi) : "l"(v));
}
__device__ __forceinline__ void fma2(ull &d, ull a, ull b) {
    asm("fma.rn.f32x2 %0, %1, %2, %0;" : "+l"(d) : "l"(a), "l"(b));
}

// One fused MLP layer over a tile of 128 points.
// Output channels CC = 32*JMAX (128 or 64). Thread (chg, ptg) computes channels
// {chg + 32j} for 8 points {8*ptg .. 8*ptg+7}. Input activations come from up to
// two smem segments (for concat/skip layers), k-major with row stride PAD.
// Weights gW are global row-major [Ktot][wstride]; we use columns
// [coloff, coloff+CC). Weight rows are staged through the smem chunk buffer.
template <int JMAX>
__device__ __forceinline__ void mlp_layer(
    const float* __restrict__ gW, int wstride, int coloff,
    const float* __restrict__ gB,
    const float* __restrict__ seg0, int n0,
    const float* __restrict__ seg1, int n1,
    float* __restrict__ dst, bool do_relu,
    float* __restrict__ Wbuf,
    int tid, int chg, int ptg)
{
    constexpr int CC = 32 * JMAX;

    ull acc[JMAX][4];
#pragma unroll
    for (int j = 0; j < JMAX; j++) {
        float b = gB[chg + 32 * j];
        ull bb = pack2(b, b);
#pragma unroll
        for (int pp = 0; pp < 4; pp++) acc[j][pp] = bb;
    }

    const float* segs[2] = { seg0, seg1 };
    int          lens[2] = { n0, n1 };

    int wrow = 0;  // running row offset into gW
#pragma unroll
    for (int si = 0; si < 2; si++) {
        const float* base = segs[si];
        int n = lens[si];
        for (int s = 0; s < n; s += WCHUNK) {
            int nk = min(WCHUNK, n - s);
            __syncthreads();  // previous chunk consumers done before Wbuf overwrite
            // cooperative load of W chunk (coalesced: consecutive i -> consecutive cols)
            for (int i = tid; i < nk * CC; i += NTHREADS) {
                int r = i / CC;
                int c = i - r * CC;
                Wbuf[i] = gW[(wrow + s + r) * wstride + coloff + c];
            }
            __syncthreads();

            const float* arow = base + s * PAD + 8 * ptg;
            const float* wrowp = Wbuf + chg;
#pragma unroll 4
            for (int kk = 0; kk < nk; kk++) {
                const ull* ap = (const ull*)(arow + kk * PAD);  // 8B-aligned (PAD even)
                ull a0 = ap[0];  // points p0,p1 (broadcast LDS.64 within warp)
                ull a1 = ap[1];
                ull a2 = ap[2];
                ull a3 = ap[3];
                const float* wk = wrowp + kk * CC;
#pragma unroll
                for (int j = 0; j < JMAX; j++) {
                    float w = wk[32 * j];      // conflict-free scalar LDS
                    ull ww = pack2(w, w);
                    fma2(acc[j][0], a0, ww);
                    fma2(acc[j][1], a1, ww);
                    fma2(acc[j][2], a2, ww);
                    fma2(acc[j][3], a3, ww);
                }
            }
        }
        wrow += n;
    }

    // epilogue: (relu) + store, k-major [c][p]
#pragma unroll
    for (int j = 0; j < JMAX; j++) {
        int c = chg + 32 * j;
        float* drow = dst + c * PAD + 8 * ptg;
#pragma unroll
        for (int pp = 0; pp < 4; pp++) {
            float lo, hi;
            unpack2(acc[j][pp], lo, hi);
            if (do_relu) { lo = fmaxf(lo, 0.f); hi = fmaxf(hi, 0.f); }
            *(ull*)(drow + 2 * pp) = pack2(lo, hi);
        }
    }
    __syncthreads();
}

__global__ void __launch_bounds__(NTHREADS, 1)
nerf_fused_kernel(
    const float* __restrict__ pts, const float* __restrict__ dirs,
    const float* __restrict__ w0, const float* __restrict__ b0,
    const float* __restrict__ w1, const float* __restrict__ b1,
    const float* __restrict__ w2, const float* __restrict__ b2,
    const float* __restrict__ w3, const float* __restrict__ b3,
    const float* __restrict__ w4, const float* __restrict__ b4,
    const float* __restrict__ w5, const float* __restrict__ b5,
    const float* __restrict__ wd, const float* __restrict__ bd,
    const float* __restrict__ wr1, const float* __restrict__ br1,
    const float* __restrict__ wr2, const float* __restrict__ br2,
    float* __restrict__ out, int n_rays)
{
    extern __shared__ float sm[];
    float* bufA = sm;                       // 128 x PAD
    float* bufB = bufA + 128 * PAD;         // 128 x PAD
    float* xyzb = bufB + 128 * PAD;         // 39  x PAD (xyz harmonic embed, kept for skip)
    float* dirb = xyzb + 39 * PAD;          // 15  x PAD (dir embed replicated across points)
    float* Wbuf = dirb + 15 * PAD;          // WCHUNK x 128

    int ray = blockIdx.x;
    int tid = threadIdx.x;
    int chg = tid & 31;
    int ptg = tid >> 5;

    // ---- embeddings ----
    if (tid < PPR) {
        int p = tid;
        const float* pp3 = pts + ((long long)ray * PPR + p) * 3;
#pragma unroll
        for (int c = 0; c < 3; c++) {
            float v = pp3[c];
            float fr = 1.f;
#pragma unroll
            for (int f = 0; f < 6; f++) {
                float s, co;
                sincosf(v * fr, &s, &co);
                xyzb[(c * 6 + f) * PAD + p] = s;
                xyzb[(18 + c * 6 + f) * PAD + p] = co;
                fr *= 2.f;
            }
            xyzb[(36 + c) * PAD + p] = v;
        }
        const float* dd = dirs + (long long)ray * 3;
#pragma unroll
        for (int c = 0; c < 3; c++) {
            float v = dd[c];
            float fr = 1.f;
#pragma unroll
            for (int f = 0; f < 2; f++) {
                float s, co;
                sincosf(v * fr, &s, &co);
                dirb[(c * 2 + f) * PAD + p] = s;
                dirb[(6 + c * 2 + f) * PAD + p] = co;
                fr *= 2.f;
            }
            dirb[(12 + c) * PAD + p] = v;
        }
    }
    __syncthreads();

    // ---- trunk MLP ----
    mlp_layer<4>(w0, 128, 0, b0, xyzb, 39, nullptr, 0, bufA, true,  Wbuf, tid, chg, ptg);
    mlp_layer<4>(w1, 128, 0, b1, bufA, 128, nullptr, 0, bufB, true, Wbuf, tid, chg, ptg);
    mlp_layer<4>(w2, 128, 0, b2, bufB, 128, nullptr, 0, bufA, true, Wbuf, tid, chg, ptg);
    // skip layer: input = concat(y, xyz_embed)
    mlp_layer<4>(w3, 128, 0, b3, bufA, 128, xyzb, 39, bufB, true,  Wbuf, tid, chg, ptg);
    mlp_layer<4>(w4, 128, 0, b4, bufB, 128, nullptr, 0, bufA, true, Wbuf, tid, chg, ptg);
    mlp_layer<4>(w5, 128, 0, b5, bufA, 128, nullptr, 0, bufB, true, Wbuf, tid, chg, ptg);

    // ---- wd: columns 1..128 (the feature part), no relu. Input stays in bufB. ----
    mlp_layer<4>(wd, 129, 1, bd + 1, bufB, 128, nullptr, 0, bufA, false, Wbuf, tid, chg, ptg);

    // ---- density: column 0 of wd, computed from bufB (layer-5 output, still intact) ----
    if (tid < PPR) {
        int p = tid;
        float s = bd[0];
#pragma unroll 4
        for (int k = 0; k < 128; k++)
            s = fmaf(bufB[k * PAD + p], __ldg(&wd[k * 129]), s);
        out[(long long)ray * PPR + p] = fmaxf(s, 0.f);
    }
    // no explicit sync needed: wr1's internal __syncthreads precedes any bufB overwrite

    // ---- wr1: input = concat(x[1:129] (bufA), dir_embed (dirb)) -> 64, relu ----
    mlp_layer<2>(wr1, 64, 0, br1, bufA, 128, dirb, 15, bufB, true, Wbuf, tid, chg, ptg);

    // ---- wr2: 64 -> 3, sigmoid ----
    if (tid < PPR) {
        int p = tid;
        float r0 = br2[0], r1 = br2[1], r2 = br2[2];
#pragma unroll 4
        for (int k = 0; k < 64; k++) {
            float h = bufB[k * PAD + p];
            r0 = fmaf(h, __ldg(&wr2[k * 3 + 0]), r0);
            r1 = fmaf(h, __ldg(&wr2[k * 3 + 1]), r1);
            r2 = fmaf(h, __ldg(&wr2[k * 3 + 2]), r2);
        }
        long long N = (long long)n_rays * PPR;
        long long base = N + ((long long)ray * PPR + p) * 3;
        out[base + 0] = 1.f / (1.f + expf(-r0));
        out[base + 1] = 1.f / (1.f + expf(-r1));
        out[base + 2] = 1.f / (1.f + expf(-r2));
    }
}

extern "C" void kernel_launch(void* const* d_in, const int* in_sizes, int n_in,
                              void* d_out, int out_size)
{
    const float* pts  = (const float*)d_in[0];
    const float* dirs = (const float*)d_in[1];
    const float* w0 = (const float*)d_in[2];
    const float* b0 = (const float*)d_in[3];
    const float* w1 = (const float*)d_in[4];
    const float* b1 = (const float*)d_in[5];
    const float* w2 = (const float*)d_in[6];
    const float* b2 = (const float*)d_in[7];
    const float* w3 = (const float*)d_in[8];
    const float* b3 = (const float*)d_in[9];
    const float* w4 = (const float*)d_in[10];
    const float* b4 = (const float*)d_in[11];
    const float* w5 = (const float*)d_in[12];
    const float* b5 = (const float*)d_in[13];
    const float* wd = (const float*)d_in[14];
    const float* bd = (const float*)d_in[15];
    const float* wr1 = (const float*)d_in[16];
    const float* br1 = (const float*)d_in[17];
    const float* wr2 = (const float*)d_in[18];
    const float* br2 = (const float*)d_in[19];
    float* out = (float*)d_out;

    int n_rays = in_sizes[1] / 3;  // directions is [n_rays, 3]

    // dynamic smem: 2 act buffers + xyz embed + dir embed + weight chunk
    size_t smem = (size_t)(2 * 128 * PAD + 39 * PAD + 15 * PAD + WCHUNK * 128) * sizeof(float);
    cudaFuncSetAttribute(nerf_fused_kernel,
                         cudaFuncAttributeMaxDynamicSharedMemorySize, (int)smem);

    nerf_fused_kernel<<<n_rays, NTHREADS, smem>>>(
        pts, dirs, w0, b0, w1, b1, w2, b2, w3, b3, w4, b4, w5, b5,
        wd, bd, wr1, br1, wr2, br2, out, n_rays);
}

// round 4
// speedup vs baseline: 5.0297x; 3.7549x over previous
#include <cuda_runtime.h>
#include <cuda_bf16.h>

typedef unsigned int u32; typedef unsigned short u16;
#define NTHR 256

// bf16 hi/lo transposed weight images, built by prep_kernel each launch.
// Per layer: Wt_hi [N][stride] bf16 then Wt_lo, strides padded (odd multiples of 16B).
__device__ __align__(16) unsigned char g_wimg[509952];

__device__ __forceinline__ u32 smaddr(const void* p) {
    u32 a; asm("{ .reg .u64 t; cvta.to.shared.u64 t, %1; cvt.u32.u64 %0, t; }" : "=r"(a) : "l"(p));
    return a;
}
__device__ __forceinline__ void ldmx4(u32& r0, u32& r1, u32& r2, u32& r3, u32 a) {
    asm volatile("ldmatrix.sync.aligned.m8n8.x4.shared.b16 {%0,%1,%2,%3}, [%4];"
                 : "=r"(r0), "=r"(r1), "=r"(r2), "=r"(r3) : "r"(a));
}
__device__ __forceinline__ void mma16816(float* c, const u32* a, u32 b0, u32 b1) {
    asm volatile("mma.sync.aligned.m16n8k16.row.col.f32.bf16.bf16.f32 "
                 "{%0,%1,%2,%3},{%4,%5,%6,%7},{%8,%9},{%0,%1,%2,%3};"
                 : "+f"(c[0]), "+f"(c[1]), "+f"(c[2]), "+f"(c[3])
                 : "r"(a[0]), "r"(a[1]), "r"(a[2]), "r"(a[3]), "r"(b0), "r"(b1));
}
__device__ __forceinline__ void cpa16(u32 d, const void* s) {
    asm volatile("cp.async.cg.shared.global [%0], [%1], 16;" :: "r"(d), "l"(s) : "memory");
}
#define CPC() asm volatile("cp.async.commit_group;" ::: "memory")
#define CPW() asm volatile("cp.async.wait_group 0;" ::: "memory")

__device__ __forceinline__ u32 pk(float lo, float hi) {
    u32 r; asm("cvt.rn.bf16x2.f32 %0, %1, %2;" : "=r"(r) : "f"(hi), "f"(lo)); return r;
}
// split f0,f1 into bf16 hi pair + bf16 lo (residual) pair
__device__ __forceinline__ void split2(float f0, float f1, u32& h, u32& l) {
    h = pk(f0, f1);
    float h0 = __uint_as_float(h << 16);
    float h1 = __uint_as_float(h & 0xffff0000u);
    l = pk(f0 - h0, f1 - h1);
}

__device__ __forceinline__ void copy_async(u32 dst, const unsigned char* src, int bytes, int tid) {
    for (int i = tid * 16; i < bytes; i += NTHR * 16) cpa16(dst + (u32)i, src + i);
    CPC();
}

// GEMM layer: M=128 (8 warps x 16 rows), N = NT2*16, K = (MF+EF)*16, 3 bf16 passes.
// AH/AL: main input frags (regs). XH/XL: extra frags (xyz embed or dir embed).
// wb = smem addr of Wt_hi image; halfB = byte offset of Wt_lo; strideEl = row stride in elems.
template <int MF, int EF, int NT2>
__device__ __forceinline__ void gemm_layer(
    float (&C)[16][4],
    const u32 (&AH)[8][4], const u32 (&AL)[8][4],
    const u32 (&XH)[3][4], const u32 (&XL)[3][4],
    u32 wb, u32 halfB, u32 strideEl, u32 thoff)
{
#pragma unroll
    for (int t = 0; t < NT2 * 2; t++) { C[t][0] = 0.f; C[t][1] = 0.f; C[t][2] = 0.f; C[t][3] = 0.f; }
    const u32 rowstep = strideEl * 32u;   // bytes per 16 N-rows
#pragma unroll 1
    for (int pass = 0; pass < 3; pass++) {
        u32 base = wb + thoff + ((pass == 2) ? halfB : 0u);
#pragma unroll
        for (int kf = 0; kf < MF + EF; kf++) {
            u32 a[4];
            if (kf < MF) {
                a[0] = (pass == 1) ? AL[kf][0] : AH[kf][0];
                a[1] = (pass == 1) ? AL[kf][1] : AH[kf][1];
                a[2] = (pass == 1) ? AL[kf][2] : AH[kf][2];
                a[3] = (pass == 1) ? AL[kf][3] : AH[kf][3];
            } else {
                a[0] = (pass == 1) ? XL[kf - MF][0] : XH[kf - MF][0];
                a[1] = (pass == 1) ? XL[kf - MF][1] : XH[kf - MF][1];
                a[2] = (pass == 1) ? XL[kf - MF][2] : XH[kf - MF][2];
                a[3] = (pass == 1) ? XL[kf - MF][3] : XH[kf - MF][3];
            }
            u32 ad = base + (u32)kf * 32u;
#pragma unroll
            for (int np = 0; np < NT2; np++) {
                u32 b0, b1, b2, b3;
                ldmx4(b0, b1, b2, b3, ad);
                mma16816(C[2 * np],     a, b0, b1);
                mma16816(C[2 * np + 1], a, b2, b3);
                ad += rowstep;
            }
        }
    }
}

// standard epilogue: C + bias (+relu) -> split into next-layer A frags
template <bool RELU>
__device__ __forceinline__ void epi_std(float (&C)[16][4], u32 (&AH)[8][4], u32 (&AL)[8][4],
                                        const float* bias, int c0)
{
#pragma unroll
    for (int j = 0; j < 8; j++) {
        float2 bA = *(const float2*)(bias + 16 * j + c0);
        float2 bB = *(const float2*)(bias + 16 * j + 8 + c0);
        float f0 = C[2*j][0] + bA.x, f1 = C[2*j][1] + bA.y;
        float f2 = C[2*j][2] + bA.x, f3 = C[2*j][3] + bA.y;
        float g0 = C[2*j+1][0] + bB.x, g1 = C[2*j+1][1] + bB.y;
        float g2 = C[2*j+1][2] + bB.x, g3 = C[2*j+1][3] + bB.y;
        if (RELU) {
            f0 = fmaxf(f0, 0.f); f1 = fmaxf(f1, 0.f); f2 = fmaxf(f2, 0.f); f3 = fmaxf(f3, 0.f);
            g0 = fmaxf(g0, 0.f); g1 = fmaxf(g1, 0.f); g2 = fmaxf(g2, 0.f); g3 = fmaxf(g3, 0.f);
        }
        split2(f0, f1, AH[j][0], AL[j][0]);
        split2(f2, f3, AH[j][1], AL[j][1]);
        split2(g0, g1, AH[j][2], AL[j][2]);
        split2(g2, g3, AH[j][3], AL[j][3]);
    }
}

// ---- prep: fp32 W[k][n] -> transposed bf16 hi/lo images Wt[n][k] with padding ----
__global__ void prep_kernel(const float* w0, const float* w1, const float* w2, const float* w3,
                            const float* w4, const float* w5, const float* wd, const float* wr1)
{
    const float* srcs[8] = {w0, w1, w2, w3, w4, w5, wd, wr1};
    const int Ks[8]   = {39, 128, 128, 167, 128, 128, 128, 143};
    const int Nn[8]   = {128, 128, 128, 128, 128, 128, 128, 64};
    const int st[8]   = {56, 136, 136, 184, 136, 136, 136, 152};
    const int wst[8]  = {128, 128, 128, 128, 128, 128, 129, 64};
    const int cof[8]  = {0, 0, 0, 0, 0, 0, 1, 0};
    const int off[8]  = {0, 28672, 98304, 167936, 262144, 331776, 401408, 471040};
    const int half[8] = {14336, 34816, 34816, 47104, 34816, 34816, 34816, 19456};
    int j = blockIdx.x;
    const float* src = srcs[j];
    int N = Nn[j], S = st[j], tot = N * S;
    for (int idx = threadIdx.x; idx < tot; idx += blockDim.x) {
        int n = idx / S, k = idx - n * S;
        float v = (k < Ks[j]) ? __ldg(src + (size_t)k * wst[j] + cof[j] + n) : 0.f;
        __nv_bfloat16 bh = __float2bfloat16(v);
        __nv_bfloat16 bl = __float2bfloat16(v - __bfloat162float(bh));
        *(u16*)(g_wimg + off[j] + (size_t)idx * 2)           = __bfloat16_as_ushort(bh);
        *(u16*)(g_wimg + off[j] + half[j] + (size_t)idx * 2) = __bfloat16_as_ushort(bl);
    }
}

__global__ void __launch_bounds__(NTHR, 1) nerf_mma_kernel(
    const float* __restrict__ pts, const float* __restrict__ dirs,
    const float* __restrict__ b0, const float* __restrict__ b1,
    const float* __restrict__ b2, const float* __restrict__ b3,
    const float* __restrict__ b4, const float* __restrict__ b5,
    const float* __restrict__ bd, const float* __restrict__ br1,
    const float* __restrict__ wd, const float* __restrict__ wr2,
    const float* __restrict__ br2, float* __restrict__ out, int ntiles)
{
    extern __shared__ __align__(16) unsigned char sm[];
    unsigned char* wbuf0 = sm;                       // 94208
    unsigned char* wbuf1 = sm + 94208;               // 94208
    float* esm  = (float*)(sm + 188416);             // 128 x 48 fp32 embed
    float* aux  = (float*)(sm + 188416 + 24576);
    float* biasS = aux;                              // 8 x 128
    float* wcS   = aux + 1024;                       // wd col 0 (128)
    float* wr2S  = aux + 1152;                       // 64 x 3
    float* br2S  = aux + 1344;                       // 3
    const u32 wb0 = smaddr(wbuf0), wb1 = smaddr(wbuf1);

    const int tid = threadIdx.x, lane = tid & 31, wid = tid >> 5;
    const int c0 = 2 * (lane & 3);
    const int r0 = 16 * wid + (lane >> 2);
    const int nadd = ((lane >> 4) << 3) + (lane & 7);     // ldmatrix row-within-pair
    const int kadd = ((lane >> 3) & 1) << 3;              // ldmatrix k-half

    // stage biases / head weights (once)
    {
        const float* bp[8] = {b0, b1, b2, b3, b4, b5, bd + 1, br1};
#pragma unroll 1
        for (int l = 0; l < 8; l++) {
            int n = (l == 7) ? 64 : 128;
            for (int i = tid; i < n; i += NTHR) biasS[l * 128 + i] = __ldg(bp[l] + i);
        }
        for (int i = tid; i < 128; i += NTHR) wcS[i] = __ldg(wd + (size_t)i * 129);
        for (int i = tid; i < 192; i += NTHR) wr2S[i] = __ldg(wr2 + i);
        if (tid < 3) br2S[tid] = __ldg(br2 + tid);
    }
    // prologue: L0 weights -> wbuf0
    copy_async(wb0, g_wimg, 28672, tid);
    CPW();
    __syncthreads();

    float C[16][4];
    u32 AH[8][4], AL[8][4], XH[3][4], XL[3][4];
    const float bd0 = __ldg(bd);
    const long long NPTS = (long long)ntiles * 128;

    for (int tile = blockIdx.x; tile < ntiles; tile += gridDim.x) {
        // ---- xyz harmonic embed into smem (threads 0..127, one point each) ----
        if (tid < 128) {
            const float* q = pts + ((long long)tile * 128 + tid) * 3;
            float* er = esm + tid * 48;
#pragma unroll
            for (int c = 0; c < 3; c++) {
                float v = q[c], fr = 1.f;
#pragma unroll
                for (int f = 0; f < 6; f++) {
                    float s, co; sincosf(v * fr, &s, &co);
                    er[c * 6 + f] = s; er[18 + c * 6 + f] = co; fr *= 2.f;
                }
                er[36 + c] = v;
            }
#pragma unroll
            for (int i = 39; i < 48; i++) er[i] = 0.f;
        }
        __syncthreads();

        // ---- xyz A-frags (kept until L3) ----
#pragma unroll
        for (int j = 0; j < 3; j++) {
            int kc = 16 * j;
            float2 p00 = *(const float2*)(esm + r0 * 48 + kc + c0);
            float2 p10 = *(const float2*)(esm + (r0 + 8) * 48 + kc + c0);
            float2 p01 = *(const float2*)(esm + r0 * 48 + kc + 8 + c0);
            float2 p11 = *(const float2*)(esm + (r0 + 8) * 48 + kc + 8 + c0);
            split2(p00.x, p00.y, XH[j][0], XL[j][0]);
            split2(p10.x, p10.y, XH[j][1], XL[j][1]);
            split2(p01.x, p01.y, XH[j][2], XL[j][2]);
            split2(p11.x, p11.y, XH[j][3], XL[j][3]);
        }

        // ---- L0 (39->128, xyz only) ----
        copy_async(wb1, g_wimg + 28672, 69632, tid);
        gemm_layer<0, 3, 8>(C, AH, AL, XH, XL, wb0, 14336, 56, (u32)((nadd * 56 + kadd) * 2));
        epi_std<true>(C, AH, AL, biasS, c0);
        CPW(); __syncthreads();

        // ---- L1 ----
        copy_async(wb0, g_wimg + 98304, 69632, tid);
        gemm_layer<8, 0, 8>(C, AH, AL, XH, XL, wb1, 34816, 136, (u32)((nadd * 136 + kadd) * 2));
        epi_std<true>(C, AH, AL, biasS + 128, c0);
        CPW(); __syncthreads();

        // ---- L2 ----
        copy_async(wb1, g_wimg + 167936, 94208, tid);
        gemm_layer<8, 0, 8>(C, AH, AL, XH, XL, wb0, 34816, 136, (u32)((nadd * 136 + kadd) * 2));
        epi_std<true>(C, AH, AL, biasS + 256, c0);
        CPW(); __syncthreads();

        // ---- L3 (skip: concat(y, xyz), K=176) ----
        copy_async(wb0, g_wimg + 262144, 69632, tid);
        gemm_layer<8, 3, 8>(C, AH, AL, XH, XL, wb1, 47104, 184, (u32)((nadd * 184 + kadd) * 2));
        epi_std<true>(C, AH, AL, biasS + 384, c0);
        CPW(); __syncthreads();

        // ---- L4 ----
        copy_async(wb1, g_wimg + 331776, 69632, tid);
        gemm_layer<8, 0, 8>(C, AH, AL, XH, XL, wb0, 34816, 136, (u32)((nadd * 136 + kadd) * 2));
        epi_std<true>(C, AH, AL, biasS + 512, c0);
        CPW(); __syncthreads();

        // ---- L5 (+fused density head) ----
        copy_async(wb0, g_wimg + 401408, 69632, tid);
        gemm_layer<8, 0, 8>(C, AH, AL, XH, XL, wb1, 34816, 136, (u32)((nadd * 136 + kadd) * 2));
        {
            const float* bias = biasS + 640;
            float d0 = 0.f, d1 = 0.f;
#pragma unroll
            for (int j = 0; j < 8; j++) {
                float2 bA = *(const float2*)(bias + 16 * j + c0);
                float2 bB = *(const float2*)(bias + 16 * j + 8 + c0);
                float2 wA = *(const float2*)(wcS + 16 * j + c0);
                float2 wB = *(const float2*)(wcS + 16 * j + 8 + c0);
                float f0 = fmaxf(C[2*j][0] + bA.x, 0.f), f1 = fmaxf(C[2*j][1] + bA.y, 0.f);
                float f2 = fmaxf(C[2*j][2] + bA.x, 0.f), f3 = fmaxf(C[2*j][3] + bA.y, 0.f);
                float g0 = fmaxf(C[2*j+1][0] + bB.x, 0.f), g1 = fmaxf(C[2*j+1][1] + bB.y, 0.f);
                float g2 = fmaxf(C[2*j+1][2] + bB.x, 0.f), g3 = fmaxf(C[2*j+1][3] + bB.y, 0.f);
                d0 += f0 * wA.x + f1 * wA.y + g0 * wB.x + g1 * wB.y;
                d1 += f2 * wA.x + f3 * wA.y + g2 * wB.x + g3 * wB.y;
                split2(f0, f1, AH[j][0], AL[j][0]);
                split2(f2, f3, AH[j][1], AL[j][1]);
                split2(g0, g1, AH[j][2], AL[j][2]);
                split2(g2, g3, AH[j][3], AL[j][3]);
            }
            d0 += __shfl_xor_sync(0xffffffffu, d0, 1); d0 += __shfl_xor_sync(0xffffffffu, d0, 2);
            d1 += __shfl_xor_sync(0xffffffffu, d1, 1); d1 += __shfl_xor_sync(0xffffffffu, d1, 2);
            if ((lane & 3) == 0) {
                long long base = (long long)tile * 128;
                out[base + r0]     = fmaxf(d0 + bd0, 0.f);
                out[base + r0 + 8] = fmaxf(d1 + bd0, 0.f);
            }
        }
        CPW(); __syncthreads();

        // ---- L6 (wd cols 1..128, NO relu) ----
        copy_async(wb1, g_wimg + 471040, 38912, tid);
        gemm_layer<8, 0, 8>(C, AH, AL, XH, XL, wb0, 34816, 136, (u32)((nadd * 136 + kadd) * 2));
        epi_std<false>(C, AH, AL, biasS + 768, c0);
        CPW(); __syncthreads();

        // ---- dir embed frag -> XH[0]/XL[0] (xyz frags dead after L3) ----
        {
            const float* dp = dirs + (long long)tile * 3;
            float d[16];
#pragma unroll
            for (int c = 0; c < 3; c++) {
                float v = __ldg(dp + c);
                float s0, cc0, s1, cc1;
                sincosf(v, &s0, &cc0); sincosf(2.f * v, &s1, &cc1);
                d[2*c] = s0; d[2*c+1] = s1; d[6+2*c] = cc0; d[7+2*c] = cc1; d[12+c] = v;
            }
            d[15] = 0.f;
            split2(d[c0], d[c0+1], XH[0][0], XL[0][0]);
            XH[0][1] = XH[0][0]; XL[0][1] = XL[0][0];
            split2(d[c0+8], d[c0+9], XH[0][2], XL[0][2]);
            XH[0][3] = XH[0][2]; XL[0][3] = XL[0][2];
        }

        // ---- L7 (wr1: concat(feat, dir) -> 64, +fused rgb head) ----
        copy_async(wb0, g_wimg, 28672, tid);   // next tile's L0
        gemm_layer<8, 1, 4>(C, AH, AL, XH, XL, wb1, 19456, 152, (u32)((nadd * 152 + kadd) * 2));
        {
            const float* bias = biasS + 896;
            float p00 = 0.f, p01 = 0.f, p02 = 0.f, p10 = 0.f, p11 = 0.f, p12 = 0.f;
#pragma unroll
            for (int j = 0; j < 8; j++) {
                float2 bA = *(const float2*)(bias + 8 * j + c0);
                float f0 = fmaxf(C[j][0] + bA.x, 0.f), f1 = fmaxf(C[j][1] + bA.y, 0.f);
                float f2 = fmaxf(C[j][2] + bA.x, 0.f), f3 = fmaxf(C[j][3] + bA.y, 0.f);
                int n = 8 * j + c0;
                const float* wA = wr2S + n * 3;
                const float* wB = wr2S + (n + 1) * 3;
                p00 += f0 * wA[0] + f1 * wB[0];
                p01 += f0 * wA[1] + f1 * wB[1];
                p02 += f0 * wA[2] + f1 * wB[2];
                p10 += f2 * wA[0] + f3 * wB[0];
                p11 += f2 * wA[1] + f3 * wB[1];
                p12 += f2 * wA[2] + f3 * wB[2];
            }
            p00 += __shfl_xor_sync(0xffffffffu, p00, 1); p00 += __shfl_xor_sync(0xffffffffu, p00, 2);
            p01 += __shfl_xor_sync(0xffffffffu, p01, 1); p01 += __shfl_xor_sync(0xffffffffu, p01, 2);
            p02 += __shfl_xor_sync(0xffffffffu, p02, 1); p02 += __shfl_xor_sync(0xffffffffu, p02, 2);
            p10 += __shfl_xor_sync(0xffffffffu, p10, 1); p10 += __shfl_xor_sync(0xffffffffu, p10, 2);
            p11 += __shfl_xor_sync(0xffffffffu, p11, 1); p11 += __shfl_xor_sync(0xffffffffu, p11, 2);
            p12 += __shfl_xor_sync(0xffffffffu, p12, 1); p12 += __shfl_xor_sync(0xffffffffu, p12, 2);
            if ((lane & 3) == 0) {
                long long pb = (long long)tile * 128;
                long long o0 = NPTS + (pb + r0) * 3;
                long long o1 = NPTS + (pb + r0 + 8) * 3;
                out[o0]     = 1.f / (1.f + expf(-(p00 + br2S[0])));
                out[o0 + 1] = 1.f / (1.f + expf(-(p01 + br2S[1])));
                out[o0 + 2] = 1.f / (1.f + expf(-(p02 + br2S[2])));
                out[o1]     = 1.f / (1.f + expf(-(p10 + br2S[0])));
                out[o1 + 1] = 1.f / (1.f + expf(-(p11 + br2S[1])));
                out[o1 + 2] = 1.f / (1.f + expf(-(p12 + br2S[2])));
            }
        }
        CPW(); __syncthreads();
    }
}

extern "C" void kernel_launch(void* const* d_in, const int* in_sizes, int n_in,
                              void* d_out, int out_size)
{
    const float* pts  = (const float*)d_in[0];
    const float* dirs = (const float*)d_in[1];
    const float *w0 = (const float*)d_in[2],  *b0 = (const float*)d_in[3];
    const float *w1 = (const float*)d_in[4],  *b1 = (const float*)d_in[5];
    const float *w2 = (const float*)d_in[6],  *b2 = (const float*)d_in[7];
    const float *w3 = (const float*)d_in[8],  *b3 = (const float*)d_in[9];
    const float *w4 = (const float*)d_in[10], *b4 = (const float*)d_in[11];
    const float *w5 = (const float*)d_in[12], *b5 = (const float*)d_in[13];
    const float *wd = (const float*)d_in[14], *bd = (const float*)d_in[15];
    const float *wr1 = (const float*)d_in[16], *br1 = (const float*)d_in[17];
    const float *wr2 = (const float*)d_in[18], *br2 = (const float*)d_in[19];
    float* out = (float*)d_out;

    int ntiles = in_sizes[1] / 3;   // rays
    int nsm = 0;
    cudaDeviceGetAttribute(&nsm, cudaDevAttrMultiProcessorCount, 0);
    if (nsm <= 0) nsm = 148;
    int grid = nsm < ntiles ? nsm : ntiles;

    size_t smem = 188416 + 24576 + 5392;   // 218384
    cudaFuncSetAttribute(nerf_mma_kernel, cudaFuncAttributeMaxDynamicSharedMemorySize, (int)smem);

    prep_kernel<<<8, 512>>>(w0, w1, w2, w3, w4, w5, wd, wr1);
    nerf_mma_kernel<<<grid, NTHR, smem>>>(pts, dirs, b0, b1, b2, b3, b4, b5,
                                          bd, br1, wd, wr2, br2, out, ntiles);
}